// round 15
// baseline (speedup 1.0000x reference)
#include <cuda_runtime.h>
#include <cuda_bf16.h>
#include <cuda_fp16.h>
#include <cstdint>

#define T_SEQ 2048
#define DIM 4096
#define KV_DIM 1024
#define NH 32
#define NKV 8
#define HD 128

// ---------------- scratch (__device__ globals; allocation-free rule) --------
__device__ __align__(16) __half g_xh[T_SEQ * DIM];
__device__ __align__(16) __half g_xl[T_SEQ * DIM];
__device__ __align__(16) __half g_yh[T_SEQ * DIM];
__device__ __align__(16) __half g_yl[T_SEQ * DIM];
__device__ __align__(16) __half g_wqh[DIM * DIM];
__device__ __align__(16) __half g_wkh[KV_DIM * DIM];
__device__ __align__(16) __half g_wvh[KV_DIM * DIM];
__device__ __align__(16) __half g_woh[DIM * DIM];
// attention operands (fp16 hi/lo)
__device__ __align__(16) __half g_qbh[T_SEQ * DIM];
__device__ __align__(16) __half g_qbl[T_SEQ * DIM];
__device__ __align__(16) __half g_kbh[T_SEQ * KV_DIM];
__device__ __align__(16) __half g_kbl[T_SEQ * KV_DIM];
__device__ __align__(16) __half g_vt[NKV * HD * T_SEQ];   // [kvh][hd][t]

// ---------------- portable PTX helpers (sm_80+ features only) ---------------
__device__ __forceinline__ uint32_t smem_u32(const void* p) {
    uint32_t a;
    asm("{ .reg .u64 t; cvta.to.shared.u64 t, %1; cvt.u32.u64 %0, t; }" : "=r"(a) : "l"(p));
    return a;
}
#define CP_ASYNC16(dst, src) \
    asm volatile("cp.async.cg.shared.global [%0], [%1], 16;" :: "r"(dst), "l"(src) : "memory")
#define CP_COMMIT() asm volatile("cp.async.commit_group;" ::: "memory")
#define CP_WAIT1()  asm volatile("cp.async.wait_group 1;" ::: "memory")
#define CP_WAIT2()  asm volatile("cp.async.wait_group 2;" ::: "memory")
#define CP_WAIT3()  asm volatile("cp.async.wait_group 3;" ::: "memory")
#define LDS32(v, addr) asm volatile("ld.shared.b32 %0, [%1];" : "=r"(v) : "r"(addr))
#define LDSM_X4(r0, r1, r2, r3, addr) \
    asm volatile("ldmatrix.sync.aligned.m8n8.x4.shared.b16 {%0,%1,%2,%3}, [%4];" \
        : "=r"(r0), "=r"(r1), "=r"(r2), "=r"(r3) : "r"(addr))

__device__ __forceinline__ void mma16816f16(float* c, const uint32_t* a, const uint32_t* b) {
    asm volatile(
        "mma.sync.aligned.m16n8k16.row.col.f32.f16.f16.f32 "
        "{%0,%1,%2,%3}, {%4,%5,%6,%7}, {%8,%9}, {%0,%1,%2,%3};"
        : "+f"(c[0]), "+f"(c[1]), "+f"(c[2]), "+f"(c[3])
        : "r"(a[0]), "r"(a[1]), "r"(a[2]), "r"(a[3]), "r"(b[0]), "r"(b[1]));
}
__device__ __forceinline__ uint32_t pack_f16(float hi, float lo) {
    uint32_t r;
    asm("cvt.rn.f16x2.f32 %0, %1, %2;" : "=r"(r) : "f"(hi), "f"(lo));
    return r;
}

// ---------------------------------------------------------------------------
// merged conversion kernel: x -> fp16 hi/lo; wq/wk/wv/wo -> fp16
// ---------------------------------------------------------------------------
#define N4_X   (T_SEQ * DIM / 4)
#define N4_WQ  (DIM * DIM / 4)
#define N4_WK  (KV_DIM * DIM / 4)
#define N4_WV  (KV_DIM * DIM / 4)
#define N4_WO  (DIM * DIM / 4)
#define N4_TOT (N4_X + N4_WQ + N4_WK + N4_WV + N4_WO)

__global__ __launch_bounds__(256) void cvt_all(
    const float* __restrict__ x,  const float* __restrict__ wq,
    const float* __restrict__ wk, const float* __restrict__ wv,
    const float* __restrict__ wo,
    __half* __restrict__ xh, __half* __restrict__ xl,
    __half* __restrict__ wqh, __half* __restrict__ wkh,
    __half* __restrict__ wvh, __half* __restrict__ woh) {
    int i = blockIdx.x * 256 + threadIdx.x;
    if (i >= N4_TOT) return;
    if (i < N4_X) {
        float4 v = ((const float4*)x)[i];
        __half h0 = __float2half(v.x), h1 = __float2half(v.y);
        __half h2 = __float2half(v.z), h3 = __float2half(v.w);
        ((__half2*)xh)[2 * i]     = __halves2half2(h0, h1);
        ((__half2*)xh)[2 * i + 1] = __halves2half2(h2, h3);
        ((__half2*)xl)[2 * i]     = __halves2half2(
            __float2half(v.x - __half2float(h0)), __float2half(v.y - __half2float(h1)));
        ((__half2*)xl)[2 * i + 1] = __halves2half2(
            __float2half(v.z - __half2float(h2)), __float2half(v.w - __half2float(h3)));
        return;
    }
    const float* src;
    __half* dst;
    int j = i - N4_X;
    if (j < N4_WQ)                          { src = wq; dst = wqh; }
    else if ((j -= N4_WQ) < N4_WK)          { src = wk; dst = wkh; }
    else if ((j -= N4_WK) < N4_WV)          { src = wv; dst = wvh; }
    else { j -= N4_WV;                        src = wo; dst = woh; }
    float4 v = ((const float4*)src)[j];
    ((__half2*)dst)[2 * j]     = __halves2half2(__float2half(v.x), __float2half(v.y));
    ((__half2*)dst)[2 * j + 1] = __halves2half2(__float2half(v.z), __float2half(v.w));
}

// ---------------------------------------------------------------------------
// fp16 2-chain GEMM v8: BK=64 chunks (4 k16-steps), CORRECT sync ordering
// (per-warp CP_WAIT *then* __syncthreads before any cross-warp smem read —
// the v7 bug was the reverse). 4-stage ring, 1 CTA/SM, fragments double-
// buffered. Accumulation order bit-identical to v4.
// ---------------------------------------------------------------------------
#define ROWP 144                   // 64 cols * 2B + 16B pad (phase banks 4r: conflict-free)
#define TILEB (128 * ROWP)         // 18432
#define STAGEB (3 * TILEB)         // 55296 (Ah, Al, Bh)
#define NSTAGE 4
#define EPIPITCH 134
#define GEMM_SMEM (NSTAGE * STAGEB)   // 221184 (>= 68608 for fp32 epilogue tile)
#define GK 4096
#define GNC 64                     // 4096 / 64

__global__ __launch_bounds__(256, 1) void gemm_fused(
    const __half* __restrict__ Ah, const __half* __restrict__ Al,
    const __half* __restrict__ B0, const __half* __restrict__ B1,
    const __half* __restrict__ B2,
    float* __restrict__ C, int mode,
    const float* __restrict__ cs, const float* __restrict__ sn,
    const int* __restrict__ spp,
    __half* __restrict__ qbh, __half* __restrict__ qbl,
    __half* __restrict__ kbh, __half* __restrict__ kbl,
    __half* __restrict__ vt) {
    extern __shared__ char smem[];
    const uint32_t sb = smem_u32(smem);
    const int tid = threadIdx.x, warp = tid >> 5, lane = tid & 31;
    const int wm = (warp & 3) << 5;
    const int wn = (warp >> 2) << 6;
    const int m0 = blockIdx.y << 7;
    const int ntg = blockIdx.x;

    const __half* Bsrc;
    int brow0;
    if (mode == 0)      { Bsrc = B0; brow0 = ntg << 7; }
    else if (ntg < 32)  { Bsrc = B0; brow0 = ntg << 7; }
    else if (ntg < 40)  { Bsrc = B1; brow0 = (ntg - 32) << 7; }
    else                { Bsrc = B2; brow0 = (ntg - 40) << 7; }

    float acc[2][8][4];
    #pragma unroll
    for (int mt = 0; mt < 2; mt++)
        #pragma unroll
        for (int nt = 0; nt < 8; nt++)
            #pragma unroll
            for (int j = 0; j < 4; j++) acc[mt][nt][j] = 0.f;

    // stage = 3 tiles of 128 rows x 64 cols (128B payload per row, pitch 144B)
    auto load_stage = [&](int kofs, int s) {
        const uint32_t base = sb + s * STAGEB;
        #pragma unroll
        for (int t = 0; t < 3; t++) {
            const __half* src = (t == 0) ? Ah : (t == 1) ? Al : Bsrc;
            const int rb = (t < 2) ? m0 : brow0;
            #pragma unroll
            for (int i = 0; i < 4; i++) {
                int idx = tid + (i << 8);           // 0..1023
                int r = idx >> 3, c8 = idx & 7;     // 128 rows x 8 16B-chunks
                uint32_t d = base + t * TILEB + r * ROWP + (c8 << 4);
                const void* g = src + (size_t)(rb + r) * GK + kofs + (c8 << 3);
                CP_ASYNC16(d, g);
            }
        }
    };

    const uint32_t aoffA = (uint32_t)(lane & 15) * ROWP + ((lane >> 4) << 4);
    const uint32_t aoffB = (uint32_t)(((lane >> 4) << 3) + (lane & 7)) * ROWP + (((lane >> 3) & 1) << 4);

    uint32_t ah[2][2][4], al[2][2][4], bh[2][8][2];
    auto ldfrag = [&](int b, uint32_t st, int ks) {
        const uint32_t kb = (uint32_t)ks << 5;      // ks*16 cols * 2B
        const uint32_t baseA = st + (uint32_t)wm * ROWP + aoffA + kb;
        const uint32_t baseB = st + 2 * TILEB + (uint32_t)wn * ROWP + aoffB + kb;
        #pragma unroll
        for (int mt = 0; mt < 2; mt++) {
            uint32_t a = baseA + (uint32_t)(mt << 4) * ROWP;
            LDSM_X4(ah[b][mt][0], ah[b][mt][1], ah[b][mt][2], ah[b][mt][3], a);
            LDSM_X4(al[b][mt][0], al[b][mt][1], al[b][mt][2], al[b][mt][3], a + TILEB);
        }
        #pragma unroll
        for (int np = 0; np < 4; np++) {
            uint32_t bb = baseB + (uint32_t)(np << 4) * ROWP;
            LDSM_X4(bh[b][2 * np][0], bh[b][2 * np][1], bh[b][2 * np + 1][0], bh[b][2 * np + 1][1], bb);
        }
    };
    auto mmafrag = [&](int b) {
        #pragma unroll
        for (int nt = 0; nt < 8; nt++)
            #pragma unroll
            for (int mt = 0; mt < 2; mt++) mma16816f16(acc[mt][nt], ah[b][mt], bh[b][nt]);
        #pragma unroll
        for (int nt = 0; nt < 8; nt++)
            #pragma unroll
            for (int mt = 0; mt < 2; mt++) mma16816f16(acc[mt][nt], al[b][mt], bh[b][nt]);
    };

    load_stage(0, 0);    CP_COMMIT();
    load_stage(64, 1);   CP_COMMIT();
    load_stage(128, 2);  CP_COMMIT();
    load_stage(192, 3);  CP_COMMIT();
    CP_WAIT3();
    __syncthreads();
    ldfrag(0, sb, 0);

    for (int c = 0; c < GNC; c++) {
        const int s = c & 3;
        const uint32_t st = sb + s * STAGEB;
        ldfrag(1, st, 1); mmafrag(0);        // ks0
        ldfrag(0, st, 2); mmafrag(1);        // ks1
        ldfrag(1, st, 3); mmafrag(0);        // ks2
        CP_WAIT2();                          // per-warp: chunk c+1 groups done
        __syncthreads();                     // publish c+1 to all warps; slot-s reads done
        if (c + 4 < GNC) load_stage((c + 4) << 6, s);
        CP_COMMIT();
        if (c + 1 < GNC) ldfrag(0, sb + ((c + 1) & 3) * STAGEB, 0);  // overlaps mma below
        mmafrag(1);                          // ks3
    }

    const int g4 = lane >> 2, t4 = lane & 3;

    if (mode == 0) {
        #pragma unroll
        for (int mt = 0; mt < 2; mt++) {
            const int row = m0 + wm + (mt << 4) + g4;
            #pragma unroll
            for (int nt = 0; nt < 8; nt++) {
                const int col = (ntg << 7) + wn + (nt << 3) + (t4 << 1);
                *(float2*)&C[(size_t)row * DIM + col]       = make_float2(acc[mt][nt][0], acc[mt][nt][1]);
                *(float2*)&C[(size_t)(row + 8) * DIM + col] = make_float2(acc[mt][nt][2], acc[mt][nt][3]);
            }
        }
        return;
    }

    __syncthreads();
    float* sf = (float*)smem;
    #pragma unroll
    for (int mt = 0; mt < 2; mt++) {
        const int r0 = wm + (mt << 4) + g4;
        #pragma unroll
        for (int nt = 0; nt < 8; nt++) {
            const int cl = wn + (nt << 3) + (t4 << 1);
            *(float2*)&sf[r0 * EPIPITCH + cl]       = make_float2(acc[mt][nt][0], acc[mt][nt][1]);
            *(float2*)&sf[(r0 + 8) * EPIPITCH + cl] = make_float2(acc[mt][nt][2], acc[mt][nt][3]);
        }
    }
    __syncthreads();

    if (ntg < 40) {
        const bool isQ = (ntg < 32);
        const int sp = *spp;
        const int d = tid & 127;
        const int dd = d & 63;
        const bool hi = d >= 64;
        const int r0 = (tid >> 7) << 6;
        const float qscale = 0.08838834764831845f;
        __half* dh = isQ ? qbh : kbh;
        __half* dl = isQ ? qbl : kbl;
        const size_t cstride = isQ ? DIM : KV_DIM;
        const size_t cbase = isQ ? (size_t)(ntg << 7) : (size_t)((ntg - 32) << 7);
        for (int r = r0; r < r0 + 64; r++) {
            const int t = m0 + r;
            float cv = cs[(size_t)(sp + t) * 64 + dd];
            float sv = sn[(size_t)(sp + t) * 64 + dd];
            float xa = sf[r * EPIPITCH + d];
            float xb = sf[r * EPIPITCH + (d ^ 64)];
            float yv = hi ? (xa * cv + xb * sv) : (xa * cv - xb * sv);
            if (isQ) yv *= qscale;
            __half hh = __float2half(yv);
            __half ll = __float2half(yv - __half2float(hh));
            size_t e = (size_t)t * cstride + cbase + d;
            dh[e] = hh;
            dl[e] = ll;
        }
    } else {
        const int kvh = ntg - 40;
        const int t = tid & 127;
        const int d0 = (tid >> 7) << 6;
        #pragma unroll 4
        for (int d = d0; d < d0 + 64; d++) {
            float v = sf[t * EPIPITCH + d];
            vt[(size_t)(kvh * HD + d) * T_SEQ + m0 + t] = __float2half(v);
        }
    }
}

// ---------------------------------------------------------------------------
// Tensor-core causal GQA flash attention (round-13 proven, unchanged).
// ---------------------------------------------------------------------------
#define BK 64
#define KP 272
#define VP 144
#define KST 17408
#define VOFF 34816
#define STG 53248
#define ATTN_SMEM (2 * STG)

__global__ __launch_bounds__(256, 1) void attn_tc(
    const __half* __restrict__ qbh, const __half* __restrict__ qbl,
    const __half* __restrict__ kbh, const __half* __restrict__ kbl,
    const __half* __restrict__ vt,
    __half* __restrict__ yh, __half* __restrict__ yl) {
    extern __shared__ char smem[];
    const uint32_t sb = smem_u32(smem);
    const int qt = gridDim.x - 1 - blockIdx.x;
    const int h = blockIdx.y, kvh = h >> 2;
    const int tid = threadIdx.x, warp = tid >> 5, lane = tid & 31;
    const int g4 = lane >> 2, t4 = lane & 3;
    const int wr0 = qt * 128 + warp * 16;
    const int ntiles = 2 * qt + 2;

    uint32_t qfh[8][4], qfl[8][4];
    {
        const uint32_t* ph = (const uint32_t*)qbh;
        const uint32_t* pl = (const uint32_t*)qbl;
        #pragma unroll
        for (int ks = 0; ks < 8; ks++)
            #pragma unroll
            for (int j = 0; j < 4; j++) {
                int row = wr0 + g4 + (j & 1) * 8;
                int col = 16 * ks + 2 * t4 + (j >> 1) * 8;
                size_t e = ((size_t)row * DIM + h * HD + col) >> 1;
                qfh[ks][j] = ph[e];
                qfl[ks][j] = pl[e];
            }
    }

    auto load_stage = [&](int kt, int s) {
        const uint32_t base = sb + s * STG;
        const int kbase = kt * BK;
        #pragma unroll
        for (int i = 0; i < 8; i++) {
            int idx = tid + (i << 8);
            int hl = idx >> 10;
            int w = idx & 1023;
            int row = w >> 4, ch = w & 15;
            const __half* src = (hl ? kbl : kbh) + (size_t)(kbase + row) * KV_DIM + kvh * HD + ch * 8;
            CP_ASYNC16(base + hl * KST + row * KP + ch * 16, src);
        }
        #pragma unroll
        for (int i = 0; i < 4; i++) {
            int idx = tid + (i << 8);
            int row = idx >> 3, ch = idx & 7;
            const __half* src = vt + (size_t)(kvh * HD + row) * T_SEQ + kbase + ch * 8;
            CP_ASYNC16(base + VOFF + row * VP + ch * 16, src);
        }
    };

    float O[16][4];
    #pragma unroll
    for (int nt = 0; nt < 16; nt++)
        #pragma unroll
        for (int j = 0; j < 4; j++) O[nt][j] = 0.f;
    float m0 = -1e30f, m1 = -1e30f, l0 = 0.f, l1 = 0.f;

    const uint32_t aoffK = (uint32_t)(((lane >> 4) << 3) + (lane & 7)) * KP + (((lane >> 3) & 1) << 4);
    const uint32_t aoffV = (uint32_t)(((lane >> 4) << 3) + (lane & 7)) * VP + (((lane >> 3) & 1) << 4);

    load_stage(0, 0); CP_COMMIT();
    load_stage(1, 1); CP_COMMIT();

    for (int kt = 0; kt < ntiles; kt++) {
        CP_WAIT1();
        __syncthreads();
        const uint32_t stp = sb + (kt & 1) * STG;
        const int kbase = kt * BK;

        float S[8][4];
        #pragma unroll
        for (int nt = 0; nt < 8; nt++)
            #pragma unroll
            for (int j = 0; j < 4; j++) S[nt][j] = 0.f;
        #pragma unroll
        for (int ks = 0; ks < 8; ks++) {
            uint32_t kfh[8][2], kfl[8][2];
            #pragma unroll
            for (int np = 0; np < 4; np++) {
                uint32_t a = stp + aoffK + (uint32_t)(np << 4) * KP + ((uint32_t)ks << 5);
                LDSM_X4(kfh[2 * np][0], kfh[2 * np][1], kfh[2 * np + 1][0], kfh[2 * np + 1][1], a);
                LDSM_X4(kfl[2 * np][0], kfl[2 * np][1], kfl[2 * np + 1][0], kfl[2 * np + 1][1], a + KST);
            }
            #pragma unroll
            for (int nt = 0; nt < 8; nt++) mma16816f16(S[nt], qfh[ks], kfh[nt]);
            #pragma unroll
            for (int nt = 0; nt < 8; nt++) mma16816f16(S[nt], qfl[ks], kfh[nt]);
            #pragma unroll
            for (int nt = 0; nt < 8; nt++) mma16816f16(S[nt], qfh[ks], kfl[nt]);
        }

        if (kbase + BK - 1 > wr0) {
            #pragma unroll
            for (int nt = 0; nt < 8; nt++) {
                int col = kbase + nt * 8 + 2 * t4;
                int rl = wr0 + g4, rh = wr0 + 8 + g4;
                if (col     > rl) S[nt][0] = -1e30f;
                if (col + 1 > rl) S[nt][1] = -1e30f;
                if (col     > rh) S[nt][2] = -1e30f;
                if (col + 1 > rh) S[nt][3] = -1e30f;
            }
        }

        float mx0 = -1e30f, mx1 = -1e30f;
        #pragma unroll
        for (int nt = 0; nt < 8; nt++) {
            mx0 = fmaxf(mx0, fmaxf(S[nt][0], S[nt][1]));
            mx1 = fmaxf(mx1, fmaxf(S[nt][2], S[nt][3]));
        }
        mx0 = fmaxf(mx0, __shfl_xor_sync(0xffffffffu, mx0, 1));
        mx0 = fmaxf(mx0, __shfl_xor_sync(0xffffffffu, mx0, 2));
        mx1 = fmaxf(mx1, __shfl_xor_sync(0xffffffffu, mx1, 1));
        mx1 = fmaxf(mx1, __shfl_xor_sync(0xffffffffu, mx1, 2));
        float mn0 = fmaxf(m0, mx0), mn1 = fmaxf(m1, mx1);
        float a0 = __expf(m0 - mn0), a1 = __expf(m1 - mn1);
        m0 = mn0; m1 = mn1;
        float ts0 = 0.f, ts1 = 0.f;
        #pragma unroll
        for (int nt = 0; nt < 8; nt++) {
            S[nt][0] = __expf(S[nt][0] - mn0);
            S[nt][1] = __expf(S[nt][1] - mn0);
            S[nt][2] = __expf(S[nt][2] - mn1);
            S[nt][3] = __expf(S[nt][3] - mn1);
            ts0 += S[nt][0] + S[nt][1];
            ts1 += S[nt][2] + S[nt][3];
        }
        ts0 += __shfl_xor_sync(0xffffffffu, ts0, 1);
        ts0 += __shfl_xor_sync(0xffffffffu, ts0, 2);
        ts1 += __shfl_xor_sync(0xffffffffu, ts1, 1);
        ts1 += __shfl_xor_sync(0xffffffffu, ts1, 2);
        l0 = l0 * a0 + ts0;
        l1 = l1 * a1 + ts1;
        #pragma unroll
        for (int nt = 0; nt < 16; nt++) {
            O[nt][0] *= a0; O[nt][1] *= a0;
            O[nt][2] *= a1; O[nt][3] *= a1;
        }

        uint32_t pk[4][4];
        #pragma unroll
        for (int ks = 0; ks < 4; ks++) {
            pk[ks][0] = pack_f16(S[2 * ks][1],     S[2 * ks][0]);
            pk[ks][1] = pack_f16(S[2 * ks][3],     S[2 * ks][2]);
            pk[ks][2] = pack_f16(S[2 * ks + 1][1], S[2 * ks + 1][0]);
            pk[ks][3] = pack_f16(S[2 * ks + 1][3], S[2 * ks + 1][2]);
        }

        #pragma unroll
        for (int ks = 0; ks < 4; ks++) {
            #pragma unroll
            for (int np = 0; np < 8; np++) {
                uint32_t a = stp + VOFF + aoffV + (uint32_t)(np << 4) * VP + ((uint32_t)ks << 5);
                uint32_t b0[2], b1[2];
                LDSM_X4(b0[0], b0[1], b1[0], b1[1], a);
                mma16816f16(O[2 * np],     pk[ks], b0);
                mma16816f16(O[2 * np + 1], pk[ks], b1);
            }
        }

        __syncthreads();
        if (kt + 2 < ntiles) load_stage(kt + 2, kt & 1);
        CP_COMMIT();
    }

    float i0 = 1.f / l0, i1 = 1.f / l1;
    #pragma unroll
    for (int nt = 0; nt < 16; nt++) {
        int col = h * HD + nt * 8 + 2 * t4;
        size_t e0 = (size_t)(wr0 + g4) * DIM + col;
        size_t e1 = (size_t)(wr0 + 8 + g4) * DIM + col;
        float v00 = O[nt][0] * i0, v01 = O[nt][1] * i0;
        float v10 = O[nt][2] * i1, v11 = O[nt][3] * i1;
        __half h00 = __float2half(v00), h01 = __float2half(v01);
        __half h10 = __float2half(v10), h11 = __float2half(v11);
        *(__half2*)(yh + e0) = __halves2half2(h00, h01);
        *(__half2*)(yh + e1) = __halves2half2(h10, h11);
        *(__half2*)(yl + e0) = __halves2half2(
            __float2half(v00 - __half2float(h00)), __float2half(v01 - __half2float(h01)));
        *(__half2*)(yl + e1) = __halves2half2(
            __float2half(v10 - __half2float(h10)), __float2half(v11 - __half2float(h11)));
    }
}

// ---------------------------------------------------------------------------
extern "C" void kernel_launch(void* const* d_in, const int* in_sizes, int n_in,
                              void* d_out, int out_size) {
    const float* x  = (const float*)d_in[0];
    const float* cs = (const float*)d_in[1];
    const float* sn = (const float*)d_in[2];
    const float* wq = (const float*)d_in[3];
    const float* wk = (const float*)d_in[4];
    const float* wv = (const float*)d_in[5];
    const float* wo = (const float*)d_in[6];
    const int*   sp = (const int*)d_in[7];
    float* out = (float*)d_out;

    __half *xh, *xl, *yh, *yl, *wqh, *wkh, *wvh, *woh;
    __half *qbh, *qbl, *kbh, *kbl, *vt;
    cudaGetSymbolAddress((void**)&xh, g_xh);   cudaGetSymbolAddress((void**)&xl, g_xl);
    cudaGetSymbolAddress((void**)&yh, g_yh);   cudaGetSymbolAddress((void**)&yl, g_yl);
    cudaGetSymbolAddress((void**)&wqh, g_wqh); cudaGetSymbolAddress((void**)&wkh, g_wkh);
    cudaGetSymbolAddress((void**)&wvh, g_wvh); cudaGetSymbolAddress((void**)&woh, g_woh);
    cudaGetSymbolAddress((void**)&qbh, g_qbh); cudaGetSymbolAddress((void**)&qbl, g_qbl);
    cudaGetSymbolAddress((void**)&kbh, g_kbh); cudaGetSymbolAddress((void**)&kbl, g_kbl);
    cudaGetSymbolAddress((void**)&vt, g_vt);

    cudaFuncSetAttribute(gemm_fused, cudaFuncAttributeMaxDynamicSharedMemorySize, GEMM_SMEM);
    cudaFuncSetAttribute(attn_tc, cudaFuncAttributeMaxDynamicSharedMemorySize, ATTN_SMEM);

    cvt_all<<<(N4_TOT + 255) / 256, 256>>>(x, wq, wk, wv, wo,
                                           xh, xl, wqh, wkh, wvh, woh);
    gemm_fused<<<dim3(48, T_SEQ / 128), 256, GEMM_SMEM>>>(
        xh, xl, wqh, wkh, wvh, nullptr, 1,
        cs, sn, sp, qbh, qbl, kbh, kbl, vt);
    attn_tc<<<dim3(T_SEQ / 128, NH), 256, ATTN_SMEM>>>(qbh, qbl, kbh, kbl, vt, yh, yl);
    gemm_fused<<<dim3(32, T_SEQ / 128), 256, GEMM_SMEM>>>(
        yh, yl, woh, nullptr, nullptr, out, 0,
        nullptr, nullptr, nullptr, nullptr, nullptr, nullptr, nullptr, nullptr);
}

// round 16
// speedup vs baseline: 1.0364x; 1.0364x over previous
#include <cuda_runtime.h>
#include <cuda_bf16.h>
#include <cuda_fp16.h>
#include <cstdint>

#define T_SEQ 2048
#define DIM 4096
#define KV_DIM 1024
#define NH 32
#define NKV 8
#define HD 128

// ---------------- scratch (__device__ globals; allocation-free rule) --------
__device__ __align__(16) __half g_xh[T_SEQ * DIM];
__device__ __align__(16) __half g_xl[T_SEQ * DIM];
__device__ __align__(16) __half g_yh[T_SEQ * DIM];
__device__ __align__(16) __half g_yl[T_SEQ * DIM];
__device__ __align__(16) __half g_wqh[DIM * DIM];
__device__ __align__(16) __half g_wkh[KV_DIM * DIM];
__device__ __align__(16) __half g_wvh[KV_DIM * DIM];
__device__ __align__(16) __half g_woh[DIM * DIM];
// attention operands (fp16 hi/lo)
__device__ __align__(16) __half g_qbh[T_SEQ * DIM];
__device__ __align__(16) __half g_qbl[T_SEQ * DIM];
__device__ __align__(16) __half g_kbh[T_SEQ * KV_DIM];
__device__ __align__(16) __half g_kbl[T_SEQ * KV_DIM];
__device__ __align__(16) __half g_vt[NKV * HD * T_SEQ];   // [kvh][hd][t]

// ---------------- portable PTX helpers (sm_80+ features only) ---------------
__device__ __forceinline__ uint32_t smem_u32(const void* p) {
    uint32_t a;
    asm("{ .reg .u64 t; cvta.to.shared.u64 t, %1; cvt.u32.u64 %0, t; }" : "=r"(a) : "l"(p));
    return a;
}
#define CP_ASYNC16(dst, src) \
    asm volatile("cp.async.cg.shared.global [%0], [%1], 16;" :: "r"(dst), "l"(src) : "memory")
#define CP_COMMIT() asm volatile("cp.async.commit_group;" ::: "memory")
#define CP_WAIT1()  asm volatile("cp.async.wait_group 1;" ::: "memory")
#define CP_WAIT2()  asm volatile("cp.async.wait_group 2;" ::: "memory")
#define CP_WAIT3()  asm volatile("cp.async.wait_group 3;" ::: "memory")
#define LDS32(v, addr) asm volatile("ld.shared.b32 %0, [%1];" : "=r"(v) : "r"(addr))
#define LDSM_X4(r0, r1, r2, r3, addr) \
    asm volatile("ldmatrix.sync.aligned.m8n8.x4.shared.b16 {%0,%1,%2,%3}, [%4];" \
        : "=r"(r0), "=r"(r1), "=r"(r2), "=r"(r3) : "r"(addr))

__device__ __forceinline__ void mma16816f16(float* c, const uint32_t* a, const uint32_t* b) {
    asm volatile(
        "mma.sync.aligned.m16n8k16.row.col.f32.f16.f16.f32 "
        "{%0,%1,%2,%3}, {%4,%5,%6,%7}, {%8,%9}, {%0,%1,%2,%3};"
        : "+f"(c[0]), "+f"(c[1]), "+f"(c[2]), "+f"(c[3])
        : "r"(a[0]), "r"(a[1]), "r"(a[2]), "r"(a[3]), "r"(b[0]), "r"(b[1]));
}
__device__ __forceinline__ uint32_t pack_f16(float hi, float lo) {
    uint32_t r;
    asm("cvt.rn.f16x2.f32 %0, %1, %2;" : "=r"(r) : "f"(hi), "f"(lo));
    return r;
}

// ---------------------------------------------------------------------------
// merged conversion kernel: x -> fp16 hi/lo; wq/wk/wv/wo -> fp16
// ---------------------------------------------------------------------------
#define N4_X   (T_SEQ * DIM / 4)
#define N4_WQ  (DIM * DIM / 4)
#define N4_WK  (KV_DIM * DIM / 4)
#define N4_WV  (KV_DIM * DIM / 4)
#define N4_WO  (DIM * DIM / 4)
#define N4_TOT (N4_X + N4_WQ + N4_WK + N4_WV + N4_WO)

__global__ __launch_bounds__(256) void cvt_all(
    const float* __restrict__ x,  const float* __restrict__ wq,
    const float* __restrict__ wk, const float* __restrict__ wv,
    const float* __restrict__ wo,
    __half* __restrict__ xh, __half* __restrict__ xl,
    __half* __restrict__ wqh, __half* __restrict__ wkh,
    __half* __restrict__ wvh, __half* __restrict__ woh) {
    int i = blockIdx.x * 256 + threadIdx.x;
    if (i >= N4_TOT) return;
    if (i < N4_X) {
        float4 v = ((const float4*)x)[i];
        __half h0 = __float2half(v.x), h1 = __float2half(v.y);
        __half h2 = __float2half(v.z), h3 = __float2half(v.w);
        ((__half2*)xh)[2 * i]     = __halves2half2(h0, h1);
        ((__half2*)xh)[2 * i + 1] = __halves2half2(h2, h3);
        ((__half2*)xl)[2 * i]     = __halves2half2(
            __float2half(v.x - __half2float(h0)), __float2half(v.y - __half2float(h1)));
        ((__half2*)xl)[2 * i + 1] = __halves2half2(
            __float2half(v.z - __half2float(h2)), __float2half(v.w - __half2float(h3)));
        return;
    }
    const float* src;
    __half* dst;
    int j = i - N4_X;
    if (j < N4_WQ)                          { src = wq; dst = wqh; }
    else if ((j -= N4_WQ) < N4_WK)          { src = wk; dst = wkh; }
    else if ((j -= N4_WK) < N4_WV)          { src = wv; dst = wvh; }
    else { j -= N4_WV;                        src = wo; dst = woh; }
    float4 v = ((const float4*)src)[j];
    ((__half2*)dst)[2 * j]     = __halves2half2(__float2half(v.x), __float2half(v.y));
    ((__half2*)dst)[2 * j + 1] = __halves2half2(__float2half(v.z), __float2half(v.w));
}

// ---------------------------------------------------------------------------
// fp16 2-chain GEMM v4 (round-13 proven best: 309us, tensor 72.9%, regs 174):
// BK=32, software-pipelined fragments, 4-stage cp.async ring, 1 CTA/SM,
// one sync per chunk between the two mma bursts.
// ---------------------------------------------------------------------------
#define ROWP 80
#define TILEB (128 * ROWP)
#define STAGEB (3 * TILEB)
#define NSTAGE 4
#define EPIPITCH 134
#define GEMM_SMEM (NSTAGE * STAGEB)
#define GK 4096
#define GNC 128

__global__ __launch_bounds__(256, 1) void gemm_fused(
    const __half* __restrict__ Ah, const __half* __restrict__ Al,
    const __half* __restrict__ B0, const __half* __restrict__ B1,
    const __half* __restrict__ B2,
    float* __restrict__ C, int mode,
    const float* __restrict__ cs, const float* __restrict__ sn,
    const int* __restrict__ spp,
    __half* __restrict__ qbh, __half* __restrict__ qbl,
    __half* __restrict__ kbh, __half* __restrict__ kbl,
    __half* __restrict__ vt) {
    extern __shared__ char smem[];
    const uint32_t sb = smem_u32(smem);
    const int tid = threadIdx.x, warp = tid >> 5, lane = tid & 31;
    const int wm = (warp & 3) << 5;
    const int wn = (warp >> 2) << 6;
    const int m0 = blockIdx.y << 7;
    const int ntg = blockIdx.x;

    const __half* Bsrc;
    int brow0;
    if (mode == 0)      { Bsrc = B0; brow0 = ntg << 7; }
    else if (ntg < 32)  { Bsrc = B0; brow0 = ntg << 7; }
    else if (ntg < 40)  { Bsrc = B1; brow0 = (ntg - 32) << 7; }
    else                { Bsrc = B2; brow0 = (ntg - 40) << 7; }

    float acc[2][8][4];
    #pragma unroll
    for (int mt = 0; mt < 2; mt++)
        #pragma unroll
        for (int nt = 0; nt < 8; nt++)
            #pragma unroll
            for (int j = 0; j < 4; j++) acc[mt][nt][j] = 0.f;

    auto load_stage = [&](int kofs, int s) {
        const uint32_t base = sb + s * STAGEB;
        #pragma unroll
        for (int t = 0; t < 3; t++) {
            const __half* src = (t == 0) ? Ah : (t == 1) ? Al : Bsrc;
            const int rb = (t < 2) ? m0 : brow0;
            #pragma unroll
            for (int i = 0; i < 2; i++) {
                int idx = tid + (i << 8);
                int r = idx >> 2, c = idx & 3;
                uint32_t d = base + t * TILEB + r * ROWP + (c << 4);
                const void* g = src + (size_t)(rb + r) * GK + kofs + (c << 3);
                CP_ASYNC16(d, g);
            }
        }
    };

    const uint32_t aoffA = (uint32_t)(lane & 15) * ROWP + ((lane >> 4) << 4);
    const uint32_t aoffB = (uint32_t)(((lane >> 4) << 3) + (lane & 7)) * ROWP + (((lane >> 3) & 1) << 4);

    uint32_t ah[2][2][4], al[2][2][4], bh[2][8][2];
    auto ldfrag = [&](int b, uint32_t st, int ks) {
        const uint32_t kb = (uint32_t)ks << 5;
        const uint32_t baseA = st + (uint32_t)wm * ROWP + aoffA + kb;
        const uint32_t baseB = st + 2 * TILEB + (uint32_t)wn * ROWP + aoffB + kb;
        #pragma unroll
        for (int mt = 0; mt < 2; mt++) {
            uint32_t a = baseA + (uint32_t)(mt << 4) * ROWP;
            LDSM_X4(ah[b][mt][0], ah[b][mt][1], ah[b][mt][2], ah[b][mt][3], a);
            LDSM_X4(al[b][mt][0], al[b][mt][1], al[b][mt][2], al[b][mt][3], a + TILEB);
        }
        #pragma unroll
        for (int np = 0; np < 4; np++) {
            uint32_t bb = baseB + (uint32_t)(np << 4) * ROWP;
            LDSM_X4(bh[b][2 * np][0], bh[b][2 * np][1], bh[b][2 * np + 1][0], bh[b][2 * np + 1][1], bb);
        }
    };
    auto mmafrag = [&](int b) {
        #pragma unroll
        for (int nt = 0; nt < 8; nt++)
            #pragma unroll
            for (int mt = 0; mt < 2; mt++) mma16816f16(acc[mt][nt], ah[b][mt], bh[b][nt]);
        #pragma unroll
        for (int nt = 0; nt < 8; nt++)
            #pragma unroll
            for (int mt = 0; mt < 2; mt++) mma16816f16(acc[mt][nt], al[b][mt], bh[b][nt]);
    };

    load_stage(0, 0);   CP_COMMIT();
    load_stage(32, 1);  CP_COMMIT();
    load_stage(64, 2);  CP_COMMIT();
    load_stage(96, 3);  CP_COMMIT();
    CP_WAIT3();
    __syncthreads();
    ldfrag(0, sb, 0);

    for (int c = 0; c < GNC; c++) {
        const int s = c & 3;
        const uint32_t st = sb + s * STAGEB;
        ldfrag(1, st, 1);
        mmafrag(0);
        CP_WAIT2();
        __syncthreads();
        if (c + 4 < GNC) load_stage((c + 4) << 5, s);
        CP_COMMIT();
        if (c + 1 < GNC) ldfrag(0, sb + ((c + 1) & 3) * STAGEB, 0);
        mmafrag(1);
    }

    const int g4 = lane >> 2, t4 = lane & 3;

    if (mode == 0) {
        #pragma unroll
        for (int mt = 0; mt < 2; mt++) {
            const int row = m0 + wm + (mt << 4) + g4;
            #pragma unroll
            for (int nt = 0; nt < 8; nt++) {
                const int col = (ntg << 7) + wn + (nt << 3) + (t4 << 1);
                *(float2*)&C[(size_t)row * DIM + col]       = make_float2(acc[mt][nt][0], acc[mt][nt][1]);
                *(float2*)&C[(size_t)(row + 8) * DIM + col] = make_float2(acc[mt][nt][2], acc[mt][nt][3]);
            }
        }
        return;
    }

    __syncthreads();
    float* sf = (float*)smem;
    #pragma unroll
    for (int mt = 0; mt < 2; mt++) {
        const int r0 = wm + (mt << 4) + g4;
        #pragma unroll
        for (int nt = 0; nt < 8; nt++) {
            const int cl = wn + (nt << 3) + (t4 << 1);
            *(float2*)&sf[r0 * EPIPITCH + cl]       = make_float2(acc[mt][nt][0], acc[mt][nt][1]);
            *(float2*)&sf[(r0 + 8) * EPIPITCH + cl] = make_float2(acc[mt][nt][2], acc[mt][nt][3]);
        }
    }
    __syncthreads();

    if (ntg < 40) {
        const bool isQ = (ntg < 32);
        const int sp = *spp;
        const int d = tid & 127;
        const int dd = d & 63;
        const bool hi = d >= 64;
        const int r0 = (tid >> 7) << 6;
        const float qscale = 0.08838834764831845f;
        __half* dh = isQ ? qbh : kbh;
        __half* dl = isQ ? qbl : kbl;
        const size_t cstride = isQ ? DIM : KV_DIM;
        const size_t cbase = isQ ? (size_t)(ntg << 7) : (size_t)((ntg - 32) << 7);
        for (int r = r0; r < r0 + 64; r++) {
            const int t = m0 + r;
            float cv = cs[(size_t)(sp + t) * 64 + dd];
            float sv = sn[(size_t)(sp + t) * 64 + dd];
            float xa = sf[r * EPIPITCH + d];
            float xb = sf[r * EPIPITCH + (d ^ 64)];
            float yv = hi ? (xa * cv + xb * sv) : (xa * cv - xb * sv);
            if (isQ) yv *= qscale;
            __half hh = __float2half(yv);
            __half ll = __float2half(yv - __half2float(hh));
            size_t e = (size_t)t * cstride + cbase + d;
            dh[e] = hh;
            dl[e] = ll;
        }
    } else {
        const int kvh = ntg - 40;
        const int t = tid & 127;
        const int d0 = (tid >> 7) << 6;
        #pragma unroll 4
        for (int d = d0; d < d0 + 64; d++) {
            float v = sf[t * EPIPITCH + d];
            vt[(size_t)(kvh * HD + d) * T_SEQ + m0 + t] = __float2half(v);
        }
    }
}

// ---------------------------------------------------------------------------
// Tensor-core causal GQA flash attention.
// v4: PV loop software-pipelined (prefetch LDSM of iteration i+1 before the
// mma of iteration i). Accumulation order per element unchanged.
// ---------------------------------------------------------------------------
#define BK 64
#define KP 272
#define VP 144
#define KST 17408
#define VOFF 34816
#define STG 53248
#define ATTN_SMEM (2 * STG)

__global__ __launch_bounds__(256, 1) void attn_tc(
    const __half* __restrict__ qbh, const __half* __restrict__ qbl,
    const __half* __restrict__ kbh, const __half* __restrict__ kbl,
    const __half* __restrict__ vt,
    __half* __restrict__ yh, __half* __restrict__ yl) {
    extern __shared__ char smem[];
    const uint32_t sb = smem_u32(smem);
    const int qt = gridDim.x - 1 - blockIdx.x;
    const int h = blockIdx.y, kvh = h >> 2;
    const int tid = threadIdx.x, warp = tid >> 5, lane = tid & 31;
    const int g4 = lane >> 2, t4 = lane & 3;
    const int wr0 = qt * 128 + warp * 16;
    const int ntiles = 2 * qt + 2;

    uint32_t qfh[8][4], qfl[8][4];
    {
        const uint32_t* ph = (const uint32_t*)qbh;
        const uint32_t* pl = (const uint32_t*)qbl;
        #pragma unroll
        for (int ks = 0; ks < 8; ks++)
            #pragma unroll
            for (int j = 0; j < 4; j++) {
                int row = wr0 + g4 + (j & 1) * 8;
                int col = 16 * ks + 2 * t4 + (j >> 1) * 8;
                size_t e = ((size_t)row * DIM + h * HD + col) >> 1;
                qfh[ks][j] = ph[e];
                qfl[ks][j] = pl[e];
            }
    }

    auto load_stage = [&](int kt, int s) {
        const uint32_t base = sb + s * STG;
        const int kbase = kt * BK;
        #pragma unroll
        for (int i = 0; i < 8; i++) {
            int idx = tid + (i << 8);
            int hl = idx >> 10;
            int w = idx & 1023;
            int row = w >> 4, ch = w & 15;
            const __half* src = (hl ? kbl : kbh) + (size_t)(kbase + row) * KV_DIM + kvh * HD + ch * 8;
            CP_ASYNC16(base + hl * KST + row * KP + ch * 16, src);
        }
        #pragma unroll
        for (int i = 0; i < 4; i++) {
            int idx = tid + (i << 8);
            int row = idx >> 3, ch = idx & 7;
            const __half* src = vt + (size_t)(kvh * HD + row) * T_SEQ + kbase + ch * 8;
            CP_ASYNC16(base + VOFF + row * VP + ch * 16, src);
        }
    };

    float O[16][4];
    #pragma unroll
    for (int nt = 0; nt < 16; nt++)
        #pragma unroll
        for (int j = 0; j < 4; j++) O[nt][j] = 0.f;
    float m0 = -1e30f, m1 = -1e30f, l0 = 0.f, l1 = 0.f;

    const uint32_t aoffK = (uint32_t)(((lane >> 4) << 3) + (lane & 7)) * KP + (((lane >> 3) & 1) << 4);
    const uint32_t aoffV = (uint32_t)(((lane >> 4) << 3) + (lane & 7)) * VP + (((lane >> 3) & 1) << 4);

    load_stage(0, 0); CP_COMMIT();
    load_stage(1, 1); CP_COMMIT();

    for (int kt = 0; kt < ntiles; kt++) {
        CP_WAIT1();
        __syncthreads();
        const uint32_t stp = sb + (kt & 1) * STG;
        const int kbase = kt * BK;

        float S[8][4];
        #pragma unroll
        for (int nt = 0; nt < 8; nt++)
            #pragma unroll
            for (int j = 0; j < 4; j++) S[nt][j] = 0.f;
        #pragma unroll
        for (int ks = 0; ks < 8; ks++) {
            uint32_t kfh[8][2], kfl[8][2];
            #pragma unroll
            for (int np = 0; np < 4; np++) {
                uint32_t a = stp + aoffK + (uint32_t)(np << 4) * KP + ((uint32_t)ks << 5);
                LDSM_X4(kfh[2 * np][0], kfh[2 * np][1], kfh[2 * np + 1][0], kfh[2 * np + 1][1], a);
                LDSM_X4(kfl[2 * np][0], kfl[2 * np][1], kfl[2 * np + 1][0], kfl[2 * np + 1][1], a + KST);
            }
            #pragma unroll
            for (int nt = 0; nt < 8; nt++) mma16816f16(S[nt], qfh[ks], kfh[nt]);
            #pragma unroll
            for (int nt = 0; nt < 8; nt++) mma16816f16(S[nt], qfl[ks], kfh[nt]);
            #pragma unroll
            for (int nt = 0; nt < 8; nt++) mma16816f16(S[nt], qfh[ks], kfl[nt]);
        }

        if (kbase + BK - 1 > wr0) {
            #pragma unroll
            for (int nt = 0; nt < 8; nt++) {
                int col = kbase + nt * 8 + 2 * t4;
                int rl = wr0 + g4, rh = wr0 + 8 + g4;
                if (col     > rl) S[nt][0] = -1e30f;
                if (col + 1 > rl) S[nt][1] = -1e30f;
                if (col     > rh) S[nt][2] = -1e30f;
                if (col + 1 > rh) S[nt][3] = -1e30f;
            }
        }

        float mx0 = -1e30f, mx1 = -1e30f;
        #pragma unroll
        for (int nt = 0; nt < 8; nt++) {
            mx0 = fmaxf(mx0, fmaxf(S[nt][0], S[nt][1]));
            mx1 = fmaxf(mx1, fmaxf(S[nt][2], S[nt][3]));
        }
        mx0 = fmaxf(mx0, __shfl_xor_sync(0xffffffffu, mx0, 1));
        mx0 = fmaxf(mx0, __shfl_xor_sync(0xffffffffu, mx0, 2));
        mx1 = fmaxf(mx1, __shfl_xor_sync(0xffffffffu, mx1, 1));
        mx1 = fmaxf(mx1, __shfl_xor_sync(0xffffffffu, mx1, 2));
        float mn0 = fmaxf(m0, mx0), mn1 = fmaxf(m1, mx1);
        float a0 = __expf(m0 - mn0), a1 = __expf(m1 - mn1);
        m0 = mn0; m1 = mn1;
        float ts0 = 0.f, ts1 = 0.f;
        #pragma unroll
        for (int nt = 0; nt < 8; nt++) {
            S[nt][0] = __expf(S[nt][0] - mn0);
            S[nt][1] = __expf(S[nt][1] - mn0);
            S[nt][2] = __expf(S[nt][2] - mn1);
            S[nt][3] = __expf(S[nt][3] - mn1);
            ts0 += S[nt][0] + S[nt][1];
            ts1 += S[nt][2] + S[nt][3];
        }
        ts0 += __shfl_xor_sync(0xffffffffu, ts0, 1);
        ts0 += __shfl_xor_sync(0xffffffffu, ts0, 2);
        ts1 += __shfl_xor_sync(0xffffffffu, ts1, 1);
        ts1 += __shfl_xor_sync(0xffffffffu, ts1, 2);
        l0 = l0 * a0 + ts0;
        l1 = l1 * a1 + ts1;
        #pragma unroll
        for (int nt = 0; nt < 16; nt++) {
            O[nt][0] *= a0; O[nt][1] *= a0;
            O[nt][2] *= a1; O[nt][3] *= a1;
        }

        uint32_t pk[4][4];
        #pragma unroll
        for (int ks = 0; ks < 4; ks++) {
            pk[ks][0] = pack_f16(S[2 * ks][1],     S[2 * ks][0]);
            pk[ks][1] = pack_f16(S[2 * ks][3],     S[2 * ks][2]);
            pk[ks][2] = pack_f16(S[2 * ks + 1][1], S[2 * ks + 1][0]);
            pk[ks][3] = pack_f16(S[2 * ks + 1][3], S[2 * ks + 1][2]);
        }

        // ---- O += P V : software-pipelined ldmatrix (prefetch i+1) ----
        {
            uint32_t vb[2][4];
            LDSM_X4(vb[0][0], vb[0][1], vb[0][2], vb[0][3], stp + VOFF + aoffV);
            #pragma unroll
            for (int it = 0; it < 32; it++) {
                if (it + 1 < 32) {
                    int ks1 = (it + 1) >> 3, np1 = (it + 1) & 7;
                    uint32_t a = stp + VOFF + aoffV + (uint32_t)(np1 << 4) * VP + ((uint32_t)ks1 << 5);
                    LDSM_X4(vb[(it + 1) & 1][0], vb[(it + 1) & 1][1],
                            vb[(it + 1) & 1][2], vb[(it + 1) & 1][3], a);
                }
                int ks = it >> 3, np = it & 7;
                mma16816f16(O[2 * np],     pk[ks], &vb[it & 1][0]);
                mma16816f16(O[2 * np + 1], pk[ks], &vb[it & 1][2]);
            }
        }

        __syncthreads();
        if (kt + 2 < ntiles) load_stage(kt + 2, kt & 1);
        CP_COMMIT();
    }

    float i0 = 1.f / l0, i1 = 1.f / l1;
    #pragma unroll
    for (int nt = 0; nt < 16; nt++) {
        int col = h * HD + nt * 8 + 2 * t4;
        size_t e0 = (size_t)(wr0 + g4) * DIM + col;
        size_t e1 = (size_t)(wr0 + 8 + g4) * DIM + col;
        float v00 = O[nt][0] * i0, v01 = O[nt][1] * i0;
        float v10 = O[nt][2] * i1, v11 = O[nt][3] * i1;
        __half h00 = __float2half(v00), h01 = __float2half(v01);
        __half h10 = __float2half(v10), h11 = __float2half(v11);
        *(__half2*)(yh + e0) = __halves2half2(h00, h01);
        *(__half2*)(yh + e1) = __halves2half2(h10, h11);
        *(__half2*)(yl + e0) = __halves2half2(
            __float2half(v00 - __half2float(h00)), __float2half(v01 - __half2float(h01)));
        *(__half2*)(yl + e1) = __halves2half2(
            __float2half(v10 - __half2float(h10)), __float2half(v11 - __half2float(h11)));
    }
}

// ---------------------------------------------------------------------------
extern "C" void kernel_launch(void* const* d_in, const int* in_sizes, int n_in,
                              void* d_out, int out_size) {
    const float* x  = (const float*)d_in[0];
    const float* cs = (const float*)d_in[1];
    const float* sn = (const float*)d_in[2];
    const float* wq = (const float*)d_in[3];
    const float* wk = (const float*)d_in[4];
    const float* wv = (const float*)d_in[5];
    const float* wo = (const float*)d_in[6];
    const int*   sp = (const int*)d_in[7];
    float* out = (float*)d_out;

    __half *xh, *xl, *yh, *yl, *wqh, *wkh, *wvh, *woh;
    __half *qbh, *qbl, *kbh, *kbl, *vt;
    cudaGetSymbolAddress((void**)&xh, g_xh);   cudaGetSymbolAddress((void**)&xl, g_xl);
    cudaGetSymbolAddress((void**)&yh, g_yh);   cudaGetSymbolAddress((void**)&yl, g_yl);
    cudaGetSymbolAddress((void**)&wqh, g_wqh); cudaGetSymbolAddress((void**)&wkh, g_wkh);
    cudaGetSymbolAddress((void**)&wvh, g_wvh); cudaGetSymbolAddress((void**)&woh, g_woh);
    cudaGetSymbolAddress((void**)&qbh, g_qbh); cudaGetSymbolAddress((void**)&qbl, g_qbl);
    cudaGetSymbolAddress((void**)&kbh, g_kbh); cudaGetSymbolAddress((void**)&kbl, g_kbl);
    cudaGetSymbolAddress((void**)&vt, g_vt);

    cudaFuncSetAttribute(gemm_fused, cudaFuncAttributeMaxDynamicSharedMemorySize, GEMM_SMEM);
    cudaFuncSetAttribute(attn_tc, cudaFuncAttributeMaxDynamicSharedMemorySize, ATTN_SMEM);

    cvt_all<<<(N4_TOT + 255) / 256, 256>>>(x, wq, wk, wv, wo,
                                           xh, xl, wqh, wkh, wvh, woh);
    gemm_fused<<<dim3(48, T_SEQ / 128), 256, GEMM_SMEM>>>(
        xh, xl, wqh, wkh, wvh, nullptr, 1,
        cs, sn, sp, qbh, qbl, kbh, kbl, vt);
    attn_tc<<<dim3(T_SEQ / 128, NH), 256, ATTN_SMEM>>>(qbh, qbl, kbh, kbl, vt, yh, yl);
    gemm_fused<<<dim3(32, T_SEQ / 128), 256, GEMM_SMEM>>>(
        yh, yl, woh, nullptr, nullptr, out, 0,
        nullptr, nullptr, nullptr, nullptr, nullptr, nullptr, nullptr, nullptr);
}

// round 17
// speedup vs baseline: 1.0458x; 1.0091x over previous
#include <cuda_runtime.h>
#include <cuda_bf16.h>
#include <cuda_fp16.h>
#include <cstdint>

#define T_SEQ 2048
#define DIM 4096
#define KV_DIM 1024
#define NH 32
#define NKV 8
#define HD 128

// ---------------- scratch (__device__ globals; allocation-free rule) --------
__device__ __align__(16) __half g_xh[T_SEQ * DIM];
__device__ __align__(16) __half g_xl[T_SEQ * DIM];
__device__ __align__(16) __half g_yh[T_SEQ * DIM];
__device__ __align__(16) __half g_yl[T_SEQ * DIM];
__device__ __align__(16) __half g_wqh[DIM * DIM];
__device__ __align__(16) __half g_wkh[KV_DIM * DIM];
__device__ __align__(16) __half g_wvh[KV_DIM * DIM];
__device__ __align__(16) __half g_woh[DIM * DIM];
// attention operands (fp16 hi/lo)
__device__ __align__(16) __half g_qbh[T_SEQ * DIM];
__device__ __align__(16) __half g_qbl[T_SEQ * DIM];
__device__ __align__(16) __half g_kbh[T_SEQ * KV_DIM];
__device__ __align__(16) __half g_kbl[T_SEQ * KV_DIM];
__device__ __align__(16) __half g_vt[NKV * HD * T_SEQ];   // [kvh][hd][t]

// ---------------- portable PTX helpers (sm_80+ features only) ---------------
__device__ __forceinline__ uint32_t smem_u32(const void* p) {
    uint32_t a;
    asm("{ .reg .u64 t; cvta.to.shared.u64 t, %1; cvt.u32.u64 %0, t; }" : "=r"(a) : "l"(p));
    return a;
}
#define CP_ASYNC16(dst, src) \
    asm volatile("cp.async.cg.shared.global [%0], [%1], 16;" :: "r"(dst), "l"(src) : "memory")
#define CP_COMMIT() asm volatile("cp.async.commit_group;" ::: "memory")
#define CP_WAIT1()  asm volatile("cp.async.wait_group 1;" ::: "memory")
#define CP_WAIT2()  asm volatile("cp.async.wait_group 2;" ::: "memory")
#define CP_WAIT3()  asm volatile("cp.async.wait_group 3;" ::: "memory")
#define LDS32(v, addr) asm volatile("ld.shared.b32 %0, [%1];" : "=r"(v) : "r"(addr))
#define LDSM_X4(r0, r1, r2, r3, addr) \
    asm volatile("ldmatrix.sync.aligned.m8n8.x4.shared.b16 {%0,%1,%2,%3}, [%4];" \
        : "=r"(r0), "=r"(r1), "=r"(r2), "=r"(r3) : "r"(addr))

__device__ __forceinline__ void mma16816f16(float* c, const uint32_t* a, const uint32_t* b) {
    asm volatile(
        "mma.sync.aligned.m16n8k16.row.col.f32.f16.f16.f32 "
        "{%0,%1,%2,%3}, {%4,%5,%6,%7}, {%8,%9}, {%0,%1,%2,%3};"
        : "+f"(c[0]), "+f"(c[1]), "+f"(c[2]), "+f"(c[3])
        : "r"(a[0]), "r"(a[1]), "r"(a[2]), "r"(a[3]), "r"(b[0]), "r"(b[1]));
}
__device__ __forceinline__ uint32_t pack_f16(float hi, float lo) {
    uint32_t r;
    asm("cvt.rn.f16x2.f32 %0, %1, %2;" : "=r"(r) : "f"(hi), "f"(lo));
    return r;
}

// ---------------------------------------------------------------------------
// merged conversion kernel: x -> fp16 hi/lo; wq/wk/wv/wo -> fp16
// ---------------------------------------------------------------------------
#define N4_X   (T_SEQ * DIM / 4)
#define N4_WQ  (DIM * DIM / 4)
#define N4_WK  (KV_DIM * DIM / 4)
#define N4_WV  (KV_DIM * DIM / 4)
#define N4_WO  (DIM * DIM / 4)
#define N4_TOT (N4_X + N4_WQ + N4_WK + N4_WV + N4_WO)

__global__ __launch_bounds__(256) void cvt_all(
    const float* __restrict__ x,  const float* __restrict__ wq,
    const float* __restrict__ wk, const float* __restrict__ wv,
    const float* __restrict__ wo,
    __half* __restrict__ xh, __half* __restrict__ xl,
    __half* __restrict__ wqh, __half* __restrict__ wkh,
    __half* __restrict__ wvh, __half* __restrict__ woh) {
    int i = blockIdx.x * 256 + threadIdx.x;
    if (i >= N4_TOT) return;
    if (i < N4_X) {
        float4 v = ((const float4*)x)[i];
        __half h0 = __float2half(v.x), h1 = __float2half(v.y);
        __half h2 = __float2half(v.z), h3 = __float2half(v.w);
        ((__half2*)xh)[2 * i]     = __halves2half2(h0, h1);
        ((__half2*)xh)[2 * i + 1] = __halves2half2(h2, h3);
        ((__half2*)xl)[2 * i]     = __halves2half2(
            __float2half(v.x - __half2float(h0)), __float2half(v.y - __half2float(h1)));
        ((__half2*)xl)[2 * i + 1] = __halves2half2(
            __float2half(v.z - __half2float(h2)), __float2half(v.w - __half2float(h3)));
        return;
    }
    const float* src;
    __half* dst;
    int j = i - N4_X;
    if (j < N4_WQ)                          { src = wq; dst = wqh; }
    else if ((j -= N4_WQ) < N4_WK)          { src = wk; dst = wkh; }
    else if ((j -= N4_WK) < N4_WV)          { src = wv; dst = wvh; }
    else { j -= N4_WV;                        src = wo; dst = woh; }
    float4 v = ((const float4*)src)[j];
    ((__half2*)dst)[2 * j]     = __halves2half2(__float2half(v.x), __float2half(v.y));
    ((__half2*)dst)[2 * j + 1] = __halves2half2(__float2half(v.z), __float2half(v.w));
}

// ---------------------------------------------------------------------------
// fp16 2-chain GEMM v4 (round-13/16 proven best: 309-311us, tensor 72.9%):
// BK=32, software-pipelined fragments, 4-stage cp.async ring, 1 CTA/SM.
// UNCHANGED — gemm structure space exhausted (rounds 12/14/15 falsified
// 2-CTA, BK=64-early-sync, BK=64-late-sync respectively).
// ---------------------------------------------------------------------------
#define ROWP 80
#define TILEB (128 * ROWP)
#define STAGEB (3 * TILEB)
#define NSTAGE 4
#define EPIPITCH 134
#define GEMM_SMEM (NSTAGE * STAGEB)
#define GK 4096
#define GNC 128

__global__ __launch_bounds__(256, 1) void gemm_fused(
    const __half* __restrict__ Ah, const __half* __restrict__ Al,
    const __half* __restrict__ B0, const __half* __restrict__ B1,
    const __half* __restrict__ B2,
    float* __restrict__ C, int mode,
    const float* __restrict__ cs, const float* __restrict__ sn,
    const int* __restrict__ spp,
    __half* __restrict__ qbh, __half* __restrict__ qbl,
    __half* __restrict__ kbh, __half* __restrict__ kbl,
    __half* __restrict__ vt) {
    extern __shared__ char smem[];
    const uint32_t sb = smem_u32(smem);
    const int tid = threadIdx.x, warp = tid >> 5, lane = tid & 31;
    const int wm = (warp & 3) << 5;
    const int wn = (warp >> 2) << 6;
    const int m0 = blockIdx.y << 7;
    const int ntg = blockIdx.x;

    const __half* Bsrc;
    int brow0;
    if (mode == 0)      { Bsrc = B0; brow0 = ntg << 7; }
    else if (ntg < 32)  { Bsrc = B0; brow0 = ntg << 7; }
    else if (ntg < 40)  { Bsrc = B1; brow0 = (ntg - 32) << 7; }
    else                { Bsrc = B2; brow0 = (ntg - 40) << 7; }

    float acc[2][8][4];
    #pragma unroll
    for (int mt = 0; mt < 2; mt++)
        #pragma unroll
        for (int nt = 0; nt < 8; nt++)
            #pragma unroll
            for (int j = 0; j < 4; j++) acc[mt][nt][j] = 0.f;

    auto load_stage = [&](int kofs, int s) {
        const uint32_t base = sb + s * STAGEB;
        #pragma unroll
        for (int t = 0; t < 3; t++) {
            const __half* src = (t == 0) ? Ah : (t == 1) ? Al : Bsrc;
            const int rb = (t < 2) ? m0 : brow0;
            #pragma unroll
            for (int i = 0; i < 2; i++) {
                int idx = tid + (i << 8);
                int r = idx >> 2, c = idx & 3;
                uint32_t d = base + t * TILEB + r * ROWP + (c << 4);
                const void* g = src + (size_t)(rb + r) * GK + kofs + (c << 3);
                CP_ASYNC16(d, g);
            }
        }
    };

    const uint32_t aoffA = (uint32_t)(lane & 15) * ROWP + ((lane >> 4) << 4);
    const uint32_t aoffB = (uint32_t)(((lane >> 4) << 3) + (lane & 7)) * ROWP + (((lane >> 3) & 1) << 4);

    uint32_t ah[2][2][4], al[2][2][4], bh[2][8][2];
    auto ldfrag = [&](int b, uint32_t st, int ks) {
        const uint32_t kb = (uint32_t)ks << 5;
        const uint32_t baseA = st + (uint32_t)wm * ROWP + aoffA + kb;
        const uint32_t baseB = st + 2 * TILEB + (uint32_t)wn * ROWP + aoffB + kb;
        #pragma unroll
        for (int mt = 0; mt < 2; mt++) {
            uint32_t a = baseA + (uint32_t)(mt << 4) * ROWP;
            LDSM_X4(ah[b][mt][0], ah[b][mt][1], ah[b][mt][2], ah[b][mt][3], a);
            LDSM_X4(al[b][mt][0], al[b][mt][1], al[b][mt][2], al[b][mt][3], a + TILEB);
        }
        #pragma unroll
        for (int np = 0; np < 4; np++) {
            uint32_t bb = baseB + (uint32_t)(np << 4) * ROWP;
            LDSM_X4(bh[b][2 * np][0], bh[b][2 * np][1], bh[b][2 * np + 1][0], bh[b][2 * np + 1][1], bb);
        }
    };
    auto mmafrag = [&](int b) {
        #pragma unroll
        for (int nt = 0; nt < 8; nt++)
            #pragma unroll
            for (int mt = 0; mt < 2; mt++) mma16816f16(acc[mt][nt], ah[b][mt], bh[b][nt]);
        #pragma unroll
        for (int nt = 0; nt < 8; nt++)
            #pragma unroll
            for (int mt = 0; mt < 2; mt++) mma16816f16(acc[mt][nt], al[b][mt], bh[b][nt]);
    };

    load_stage(0, 0);   CP_COMMIT();
    load_stage(32, 1);  CP_COMMIT();
    load_stage(64, 2);  CP_COMMIT();
    load_stage(96, 3);  CP_COMMIT();
    CP_WAIT3();
    __syncthreads();
    ldfrag(0, sb, 0);

    for (int c = 0; c < GNC; c++) {
        const int s = c & 3;
        const uint32_t st = sb + s * STAGEB;
        ldfrag(1, st, 1);
        mmafrag(0);
        CP_WAIT2();
        __syncthreads();
        if (c + 4 < GNC) load_stage((c + 4) << 5, s);
        CP_COMMIT();
        if (c + 1 < GNC) ldfrag(0, sb + ((c + 1) & 3) * STAGEB, 0);
        mmafrag(1);
    }

    const int g4 = lane >> 2, t4 = lane & 3;

    if (mode == 0) {
        #pragma unroll
        for (int mt = 0; mt < 2; mt++) {
            const int row = m0 + wm + (mt << 4) + g4;
            #pragma unroll
            for (int nt = 0; nt < 8; nt++) {
                const int col = (ntg << 7) + wn + (nt << 3) + (t4 << 1);
                *(float2*)&C[(size_t)row * DIM + col]       = make_float2(acc[mt][nt][0], acc[mt][nt][1]);
                *(float2*)&C[(size_t)(row + 8) * DIM + col] = make_float2(acc[mt][nt][2], acc[mt][nt][3]);
            }
        }
        return;
    }

    __syncthreads();
    float* sf = (float*)smem;
    #pragma unroll
    for (int mt = 0; mt < 2; mt++) {
        const int r0 = wm + (mt << 4) + g4;
        #pragma unroll
        for (int nt = 0; nt < 8; nt++) {
            const int cl = wn + (nt << 3) + (t4 << 1);
            *(float2*)&sf[r0 * EPIPITCH + cl]       = make_float2(acc[mt][nt][0], acc[mt][nt][1]);
            *(float2*)&sf[(r0 + 8) * EPIPITCH + cl] = make_float2(acc[mt][nt][2], acc[mt][nt][3]);
        }
    }
    __syncthreads();

    if (ntg < 40) {
        const bool isQ = (ntg < 32);
        const int sp = *spp;
        const int d = tid & 127;
        const int dd = d & 63;
        const bool hi = d >= 64;
        const int r0 = (tid >> 7) << 6;
        const float qscale = 0.08838834764831845f;
        __half* dh = isQ ? qbh : kbh;
        __half* dl = isQ ? qbl : kbl;
        const size_t cstride = isQ ? DIM : KV_DIM;
        const size_t cbase = isQ ? (size_t)(ntg << 7) : (size_t)((ntg - 32) << 7);
        for (int r = r0; r < r0 + 64; r++) {
            const int t = m0 + r;
            float cv = cs[(size_t)(sp + t) * 64 + dd];
            float sv = sn[(size_t)(sp + t) * 64 + dd];
            float xa = sf[r * EPIPITCH + d];
            float xb = sf[r * EPIPITCH + (d ^ 64)];
            float yv = hi ? (xa * cv + xb * sv) : (xa * cv - xb * sv);
            if (isQ) yv *= qscale;
            __half hh = __float2half(yv);
            __half ll = __float2half(yv - __half2float(hh));
            size_t e = (size_t)t * cstride + cbase + d;
            dh[e] = hh;
            dl[e] = ll;
        }
    } else {
        const int kvh = ntg - 40;
        const int t = tid & 127;
        const int d0 = (tid >> 7) << 6;
        #pragma unroll 4
        for (int d = d0; d < d0 + 64; d++) {
            float v = sf[t * EPIPITCH + d];
            vt[(size_t)(kvh * HD + d) * T_SEQ + m0 + t] = __float2half(v);
        }
    }
}

// ---------------------------------------------------------------------------
// Tensor-core causal GQA flash attention.
// v5: 3-stage cp.async ring, ONE sync per key-tile (trailing overwrite-guard
// sync deleted — overwrite target is the tile-(kt-1) slot, retired by the
// leading sync), loads issued before compute. Math order unchanged.
// ---------------------------------------------------------------------------
#define BK 64
#define KP 272
#define VP 144
#define KST 17408
#define VOFF 34816
#define STG 53248
#define ATTN_SMEM (3 * STG)          // 159744

__global__ __launch_bounds__(256, 1) void attn_tc(
    const __half* __restrict__ qbh, const __half* __restrict__ qbl,
    const __half* __restrict__ kbh, const __half* __restrict__ kbl,
    const __half* __restrict__ vt,
    __half* __restrict__ yh, __half* __restrict__ yl) {
    extern __shared__ char smem[];
    const uint32_t sb = smem_u32(smem);
    const int qt = gridDim.x - 1 - blockIdx.x;
    const int h = blockIdx.y, kvh = h >> 2;
    const int tid = threadIdx.x, warp = tid >> 5, lane = tid & 31;
    const int g4 = lane >> 2, t4 = lane & 3;
    const int wr0 = qt * 128 + warp * 16;
    const int ntiles = 2 * qt + 2;

    uint32_t qfh[8][4], qfl[8][4];
    {
        const uint32_t* ph = (const uint32_t*)qbh;
        const uint32_t* pl = (const uint32_t*)qbl;
        #pragma unroll
        for (int ks = 0; ks < 8; ks++)
            #pragma unroll
            for (int j = 0; j < 4; j++) {
                int row = wr0 + g4 + (j & 1) * 8;
                int col = 16 * ks + 2 * t4 + (j >> 1) * 8;
                size_t e = ((size_t)row * DIM + h * HD + col) >> 1;
                qfh[ks][j] = ph[e];
                qfl[ks][j] = pl[e];
            }
    }

    auto load_stage = [&](int kt, int s) {
        const uint32_t base = sb + s * STG;
        const int kbase = kt * BK;
        #pragma unroll
        for (int i = 0; i < 8; i++) {
            int idx = tid + (i << 8);
            int hl = idx >> 10;
            int w = idx & 1023;
            int row = w >> 4, ch = w & 15;
            const __half* src = (hl ? kbl : kbh) + (size_t)(kbase + row) * KV_DIM + kvh * HD + ch * 8;
            CP_ASYNC16(base + hl * KST + row * KP + ch * 16, src);
        }
        #pragma unroll
        for (int i = 0; i < 4; i++) {
            int idx = tid + (i << 8);
            int row = idx >> 3, ch = idx & 7;
            const __half* src = vt + (size_t)(kvh * HD + row) * T_SEQ + kbase + ch * 8;
            CP_ASYNC16(base + VOFF + row * VP + ch * 16, src);
        }
    };

    float O[16][4];
    #pragma unroll
    for (int nt = 0; nt < 16; nt++)
        #pragma unroll
        for (int j = 0; j < 4; j++) O[nt][j] = 0.f;
    float m0 = -1e30f, m1 = -1e30f, l0 = 0.f, l1 = 0.f;

    const uint32_t aoffK = (uint32_t)(((lane >> 4) << 3) + (lane & 7)) * KP + (((lane >> 3) & 1) << 4);
    const uint32_t aoffV = (uint32_t)(((lane >> 4) << 3) + (lane & 7)) * VP + (((lane >> 3) & 1) << 4);

    // prologue: tiles 0 and 1 (ntiles >= 2 always)
    load_stage(0, 0); CP_COMMIT();
    load_stage(1, 1); CP_COMMIT();

    int slot = 0;   // slot of tile kt (kt % 3)
    for (int kt = 0; kt < ntiles; kt++) {
        CP_WAIT1();                       // per-warp: tile kt complete (kt+1 may pend)
        __syncthreads();                  // publish tile kt; retire tile kt-1 reads
        // prefetch tile kt+2 into the slot tile kt-1 occupied ((kt+2)%3 == (kt-1)%3)
        {
            int s2 = slot + 2; if (s2 >= 3) s2 -= 3;
            if (kt + 2 < ntiles) load_stage(kt + 2, s2);
            CP_COMMIT();                  // unconditional: keeps group accounting uniform
        }
        const uint32_t stp = sb + slot * STG;
        const int kbase = kt * BK;

        float S[8][4];
        #pragma unroll
        for (int nt = 0; nt < 8; nt++)
            #pragma unroll
            for (int j = 0; j < 4; j++) S[nt][j] = 0.f;
        #pragma unroll
        for (int ks = 0; ks < 8; ks++) {
            uint32_t kfh[8][2], kfl[8][2];
            #pragma unroll
            for (int np = 0; np < 4; np++) {
                uint32_t a = stp + aoffK + (uint32_t)(np << 4) * KP + ((uint32_t)ks << 5);
                LDSM_X4(kfh[2 * np][0], kfh[2 * np][1], kfh[2 * np + 1][0], kfh[2 * np + 1][1], a);
                LDSM_X4(kfl[2 * np][0], kfl[2 * np][1], kfl[2 * np + 1][0], kfl[2 * np + 1][1], a + KST);
            }
            #pragma unroll
            for (int nt = 0; nt < 8; nt++) mma16816f16(S[nt], qfh[ks], kfh[nt]);
            #pragma unroll
            for (int nt = 0; nt < 8; nt++) mma16816f16(S[nt], qfl[ks], kfh[nt]);
            #pragma unroll
            for (int nt = 0; nt < 8; nt++) mma16816f16(S[nt], qfh[ks], kfl[nt]);
        }

        if (kbase + BK - 1 > wr0) {
            #pragma unroll
            for (int nt = 0; nt < 8; nt++) {
                int col = kbase + nt * 8 + 2 * t4;
                int rl = wr0 + g4, rh = wr0 + 8 + g4;
                if (col     > rl) S[nt][0] = -1e30f;
                if (col + 1 > rl) S[nt][1] = -1e30f;
                if (col     > rh) S[nt][2] = -1e30f;
                if (col + 1 > rh) S[nt][3] = -1e30f;
            }
        }

        float mx0 = -1e30f, mx1 = -1e30f;
        #pragma unroll
        for (int nt = 0; nt < 8; nt++) {
            mx0 = fmaxf(mx0, fmaxf(S[nt][0], S[nt][1]));
            mx1 = fmaxf(mx1, fmaxf(S[nt][2], S[nt][3]));
        }
        mx0 = fmaxf(mx0, __shfl_xor_sync(0xffffffffu, mx0, 1));
        mx0 = fmaxf(mx0, __shfl_xor_sync(0xffffffffu, mx0, 2));
        mx1 = fmaxf(mx1, __shfl_xor_sync(0xffffffffu, mx1, 1));
        mx1 = fmaxf(mx1, __shfl_xor_sync(0xffffffffu, mx1, 2));
        float mn0 = fmaxf(m0, mx0), mn1 = fmaxf(m1, mx1);
        float a0 = __expf(m0 - mn0), a1 = __expf(m1 - mn1);
        m0 = mn0; m1 = mn1;
        float ts0 = 0.f, ts1 = 0.f;
        #pragma unroll
        for (int nt = 0; nt < 8; nt++) {
            S[nt][0] = __expf(S[nt][0] - mn0);
            S[nt][1] = __expf(S[nt][1] - mn0);
            S[nt][2] = __expf(S[nt][2] - mn1);
            S[nt][3] = __expf(S[nt][3] - mn1);
            ts0 += S[nt][0] + S[nt][1];
            ts1 += S[nt][2] + S[nt][3];
        }
        ts0 += __shfl_xor_sync(0xffffffffu, ts0, 1);
        ts0 += __shfl_xor_sync(0xffffffffu, ts0, 2);
        ts1 += __shfl_xor_sync(0xffffffffu, ts1, 1);
        ts1 += __shfl_xor_sync(0xffffffffu, ts1, 2);
        l0 = l0 * a0 + ts0;
        l1 = l1 * a1 + ts1;
        #pragma unroll
        for (int nt = 0; nt < 16; nt++) {
            O[nt][0] *= a0; O[nt][1] *= a0;
            O[nt][2] *= a1; O[nt][3] *= a1;
        }

        uint32_t pk[4][4];
        #pragma unroll
        for (int ks = 0; ks < 4; ks++) {
            pk[ks][0] = pack_f16(S[2 * ks][1],     S[2 * ks][0]);
            pk[ks][1] = pack_f16(S[2 * ks][3],     S[2 * ks][2]);
            pk[ks][2] = pack_f16(S[2 * ks + 1][1], S[2 * ks + 1][0]);
            pk[ks][3] = pack_f16(S[2 * ks + 1][3], S[2 * ks + 1][2]);
        }

        // ---- O += P V : software-pipelined ldmatrix (prefetch i+1) ----
        {
            uint32_t vb[2][4];
            LDSM_X4(vb[0][0], vb[0][1], vb[0][2], vb[0][3], stp + VOFF + aoffV);
            #pragma unroll
            for (int it = 0; it < 32; it++) {
                if (it + 1 < 32) {
                    int ks1 = (it + 1) >> 3, np1 = (it + 1) & 7;
                    uint32_t a = stp + VOFF + aoffV + (uint32_t)(np1 << 4) * VP + ((uint32_t)ks1 << 5);
                    LDSM_X4(vb[(it + 1) & 1][0], vb[(it + 1) & 1][1],
                            vb[(it + 1) & 1][2], vb[(it + 1) & 1][3], a);
                }
                int ks = it >> 3, np = it & 7;
                mma16816f16(O[2 * np],     pk[ks], &vb[it & 1][0]);
                mma16816f16(O[2 * np + 1], pk[ks], &vb[it & 1][2]);
            }
        }

        if (++slot == 3) slot = 0;
    }

    float i0 = 1.f / l0, i1 = 1.f / l1;
    #pragma unroll
    for (int nt = 0; nt < 16; nt++) {
        int col = h * HD + nt * 8 + 2 * t4;
        size_t e0 = (size_t)(wr0 + g4) * DIM + col;
        size_t e1 = (size_t)(wr0 + 8 + g4) * DIM + col;
        float v00 = O[nt][0] * i0, v01 = O[nt][1] * i0;
        float v10 = O[nt][2] * i1, v11 = O[nt][3] * i1;
        __half h00 = __float2half(v00), h01 = __float2half(v01);
        __half h10 = __float2half(v10), h11 = __float2half(v11);
        *(__half2*)(yh + e0) = __halves2half2(h00, h01);
        *(__half2*)(yh + e1) = __halves2half2(h10, h11);
        *(__half2*)(yl + e0) = __halves2half2(
            __float2half(v00 - __half2float(h00)), __float2half(v01 - __half2float(h01)));
        *(__half2*)(yl + e1) = __halves2half2(
            __float2half(v10 - __half2float(h10)), __float2half(v11 - __half2float(h11)));
    }
}

// ---------------------------------------------------------------------------
extern "C" void kernel_launch(void* const* d_in, const int* in_sizes, int n_in,
                              void* d_out, int out_size) {
    const float* x  = (const float*)d_in[0];
    const float* cs = (const float*)d_in[1];
    const float* sn = (const float*)d_in[2];
    const float* wq = (const float*)d_in[3];
    const float* wk = (const float*)d_in[4];
    const float* wv = (const float*)d_in[5];
    const float* wo = (const float*)d_in[6];
    const int*   sp = (const int*)d_in[7];
    float* out = (float*)d_out;

    __half *xh, *xl, *yh, *yl, *wqh, *wkh, *wvh, *woh;
    __half *qbh, *qbl, *kbh, *kbl, *vt;
    cudaGetSymbolAddress((void**)&xh, g_xh);   cudaGetSymbolAddress((void**)&xl, g_xl);
    cudaGetSymbolAddress((void**)&yh, g_yh);   cudaGetSymbolAddress((void**)&yl, g_yl);
    cudaGetSymbolAddress((void**)&wqh, g_wqh); cudaGetSymbolAddress((void**)&wkh, g_wkh);
    cudaGetSymbolAddress((void**)&wvh, g_wvh); cudaGetSymbolAddress((void**)&woh, g_woh);
    cudaGetSymbolAddress((void**)&qbh, g_qbh); cudaGetSymbolAddress((void**)&qbl, g_qbl);
    cudaGetSymbolAddress((void**)&kbh, g_kbh); cudaGetSymbolAddress((void**)&kbl, g_kbl);
    cudaGetSymbolAddress((void**)&vt, g_vt);

    cudaFuncSetAttribute(gemm_fused, cudaFuncAttributeMaxDynamicSharedMemorySize, GEMM_SMEM);
    cudaFuncSetAttribute(attn_tc, cudaFuncAttributeMaxDynamicSharedMemorySize, ATTN_SMEM);

    cvt_all<<<(N4_TOT + 255) / 256, 256>>>(x, wq, wk, wv, wo,
                                           xh, xl, wqh, wkh, wvh, woh);
    gemm_fused<<<dim3(48, T_SEQ / 128), 256, GEMM_SMEM>>>(
        xh, xl, wqh, wkh, wvh, nullptr, 1,
        cs, sn, sp, qbh, qbl, kbh, kbl, vt);
    attn_tc<<<dim3(T_SEQ / 128, NH), 256, ATTN_SMEM>>>(qbh, qbl, kbh, kbl, vt, yh, yl);
    gemm_fused<<<dim3(32, T_SEQ / 128), 256, GEMM_SMEM>>>(
        yh, yl, woh, nullptr, nullptr, out, 0,
        nullptr, nullptr, nullptr, nullptr, nullptr, nullptr, nullptr, nullptr);
}